// round 17
// baseline (speedup 1.0000x reference)
#include <cuda_runtime.h>
#include <cuda_fp16.h>
#include <cstdint>

#define B_   4
#define S_   256
#define H_   768
#define KW   1024   // 4*256 : step-2 K (4 c-blocks of 256)

#define NBLK 592    // 148 SMs x 4 CTAs — guaranteed co-resident (GB300: 152 SMs)

// ---------------- static device scratch -------------------------------------
__device__ __align__(256) __half g_h[B_ * S_ * H_];      // hidden fp16 [1024][768]
__device__ __align__(256) __half g_bas[4 * H_ * H_];     // basic fp16 [c][h][o]
__device__ __align__(256) __half g_self[H_ * H_];        // selfw^T fp16 [h][o]
__device__ __align__(256) __half g_W[B_ * S_ * KW];      // W [b][i][c*256+j]
__device__ __align__(256) __half g_hb2[4 * B_ * S_ * H_];// hb slot-major [slot][1024][768]
__device__ __align__(256) int    g_relsT[B_ * S_ * S_];  // rels transposed
__device__ unsigned g_bar_count = 0;
__device__ unsigned g_bar_sense = 0;

// ---------------- helpers ---------------------------------------------------
__device__ __forceinline__ uint32_t s2u(const void* p) {
    uint32_t a;
    asm("{ .reg .u64 t; cvta.to.shared.u64 t, %1; cvt.u32.u64 %0, t; }"
        : "=r"(a) : "l"(p));
    return a;
}
__device__ __forceinline__ void cp16(uint32_t dst, const void* src) {
    asm volatile("cp.async.cg.shared.global [%0], [%1], 16;"
                 :: "r"(dst), "l"(src) : "memory");
}
__device__ __forceinline__ void ldsm4(uint32_t* r, uint32_t addr) {
    asm volatile("ldmatrix.sync.aligned.m8n8.x4.shared.b16 {%0,%1,%2,%3}, [%4];"
                 : "=r"(r[0]), "=r"(r[1]), "=r"(r[2]), "=r"(r[3]) : "r"(addr));
}
__device__ __forceinline__ void ldsm4t(uint32_t* r, uint32_t addr) {
    asm volatile("ldmatrix.sync.aligned.m8n8.x4.trans.shared.b16 {%0,%1,%2,%3}, [%4];"
                 : "=r"(r[0]), "=r"(r[1]), "=r"(r[2]), "=r"(r[3]) : "r"(addr));
}
__device__ __forceinline__ void mma_f16(float* d, const uint32_t* a,
                                        uint32_t b0, uint32_t b1) {
    asm volatile("mma.sync.aligned.m16n8k16.row.col.f32.f16.f16.f32 "
                 "{%0,%1,%2,%3}, {%4,%5,%6,%7}, {%8,%9}, {%0,%1,%2,%3};"
                 : "+f"(d[0]), "+f"(d[1]), "+f"(d[2]), "+f"(d[3])
                 : "r"(a[0]), "r"(a[1]), "r"(a[2]), "r"(a[3]), "r"(b0), "r"(b1));
}
__device__ __forceinline__ void red2(float* p, float x, float y) {
    asm volatile("red.global.add.v2.f32 [%0], {%1, %2};"
                 :: "l"(p), "f"(x), "f"(y) : "memory");
}

// ---------------- device-wide sense-reversing barrier ------------------------
__device__ __forceinline__ void grid_barrier(unsigned* lsense) {
    __threadfence();      // publish all this thread's global writes
    __syncthreads();
    if (threadIdx.x == 0) {
        const unsigned target = *lsense ^ 1u;
        if (atomicAdd(&g_bar_count, 1u) == NBLK - 1u) {
            atomicExch(&g_bar_count, 0u);
            __threadfence();
            *((volatile unsigned*)&g_bar_sense) = target;
        } else {
            while (*((volatile unsigned*)&g_bar_sense) != target) { }
            __threadfence();
        }
    }
    __syncthreads();
    *lsense ^= 1u;
}

// ---------------- GEMM geometry ----------------------------------------------
#define A_PITCH 80
#define HB_BP   272
#define HB_ABUF (64 * A_PITCH)               // 5120
#define HB_BBUF (32 * HB_BP)                 // 8704
#define HB_STG  (HB_ABUF + HB_BBUF)          // 13824
#define OUT_BP   144
#define OUT_BBUF (32 * OUT_BP)               // 4608
#define OUT_STG  (HB_ABUF + OUT_BBUF)        // 9728
#define SMEM_BYTES (3 * HB_STG)              // 41472 (< 48K static limit)

__device__ __forceinline__ void ld_a32(const __half* __restrict__ src, int ld,
                                       uint32_t s, int t) {
    #pragma unroll
    for (int u = 0; u < 2; u++) {
        const int id = t + 128 * u;
        const int r = id >> 2, seg = id & 3;
        cp16(s + r * A_PITCH + seg * 16, src + (size_t)r * ld + seg * 8);
    }
}
template<int NCOLS, int BP>
__device__ __forceinline__ void ld_b32(const __half* __restrict__ src, int ld,
                                       uint32_t s, int t) {
    #pragma unroll
    for (int u = 0; u < 32 * (NCOLS / 8) / 128; u++) {
        const int id = t + 128 * u;
        const int k = id / (NCOLS / 8), q = id % (NCOLS / 8);
        cp16(s + k * BP + q * 16, src + (size_t)k * ld + q * 8);
    }
}

template<int BP, int NG>
__device__ __forceinline__ void sub_t(uint32_t a_s, uint32_t b_s,
                                      float acc[2][NG * 2][4],
                                      int lane, int wm, int wn)
{
    const int arow = wm * 32 + (lane & 15);
    const uint32_t abase = a_s + (uint32_t)arow * A_PITCH + (uint32_t)(lane >> 4) * 16;
    uint32_t ah[2][4], bh[NG][4];
    ldsm4(ah[0], abase);
    ldsm4(ah[1], abase + 16 * A_PITCH);
    const int krow = (lane & 7) | ((lane >> 1) & 8);
    const int noff = (lane & 8) ? 16 : 0;
    #pragma unroll
    for (int g = 0; g < NG; g++)
        ldsm4t(bh[g], b_s + (uint32_t)krow * BP + (uint32_t)(wn * (NG * 32) + g * 32) + noff);
    #pragma unroll
    for (int mt = 0; mt < 2; mt++)
        #pragma unroll
        for (int g = 0; g < NG; g++)
            #pragma unroll
            for (int s = 0; s < 2; s++)
                mma_f16(acc[mt][g * 2 + s], ah[mt], bh[g][s], bh[g][s + 2]);
}

// ---------------- phase-1 items (prep) ---------------------------------------
#define P1_CONV_H 384    // hidden: 196608 float4 / 512 per item
#define P1_CONV_B 1152   // basic
#define P1_SELF   576    // 24x24 32x32 transpose tiles
#define P1_RELS   256
#define P1_ITEMS  (P1_CONV_H + P1_CONV_B + P1_SELF + P1_RELS)  // 2368

__device__ __forceinline__ void conv_item(const float* __restrict__ src,
                                          __half* __restrict__ dst, int item, int t) {
    const int base = item * 512;
    #pragma unroll
    for (int u = 0; u < 4; u++) {
        const int i = base + t + 128 * u;
        float4 v = reinterpret_cast<const float4*>(src)[i];
        __half2 a = __floats2half2_rn(v.x, v.y);
        __half2 b = __floats2half2_rn(v.z, v.w);
        uint2 p;
        p.x = *reinterpret_cast<uint32_t*>(&a);
        p.y = *reinterpret_cast<uint32_t*>(&b);
        reinterpret_cast<uint2*>(dst)[i] = p;
    }
}

__device__ void self_item(const float* __restrict__ selfw, int tl, int t, char* sm) {
    float (*tile)[33] = reinterpret_cast<float(*)[33]>(sm);
    const int h0 = (tl % 24) * 32, o0 = (tl / 24) * 32;
    const int tx = t & 31, ty = t >> 5;
    #pragma unroll
    for (int r = 0; r < 8; r++)
        tile[ty + 4 * r][tx] = selfw[(size_t)(o0 + ty + 4 * r) * H_ + h0 + tx];
    __syncthreads();
    #pragma unroll
    for (int r = 0; r < 8; r++)
        g_self[(size_t)(h0 + ty + 4 * r) * H_ + o0 + tx] =
            __float2half(tile[tx][ty + 4 * r]);
    __syncthreads();
}

__device__ void rels_item(const int* __restrict__ rels, int id, int t, char* sm) {
    int (*tile)[33] = reinterpret_cast<int(*)[33]>(sm);
    const int b = id >> 6, tl = id & 63;
    const int j0 = (tl & 7) * 32, i0 = (tl >> 3) * 32;
    const int tx = t & 31, ty = t >> 5;
    #pragma unroll
    for (int r = 0; r < 8; r++)
        tile[ty + 4 * r][tx] = rels[((size_t)b * S_ + i0 + ty + 4 * r) * S_ + j0 + tx];
    __syncthreads();
    #pragma unroll
    for (int r = 0; r < 8; r++)
        g_relsT[((size_t)b * S_ + j0 + ty + 4 * r) * S_ + i0 + tx] = tile[tx][ty + 4 * r];
    __syncthreads();
}

// ---------------- phase-2 items ----------------------------------------------
#define P2_HB 480
#define P2_ITEMS (P2_HB + B_ * S_)   // 480 + 1024 = 1504

__device__ void bw_item(const int* __restrict__ rels,
                        const float* __restrict__ rel_weight,
                        int id, int t, char* sm)
{
    const int b = id >> 8;
    const int i = id & 255;
    int*   cf    = reinterpret_cast<int*>(sm);
    int*   cr    = cf + 32;
    float* inv_f = reinterpret_cast<float*>(cr + 32);
    float* inv_r = inv_f + 32;
    float* rw    = inv_r + 32;   // 256 floats

    if (t < 32) { cf[t] = 0; cr[t] = 0; }
    rw[t] = rel_weight[t];
    rw[t + 128] = rel_weight[t + 128];
    __syncthreads();

    int lf[2], lr[2];
    #pragma unroll
    for (int u = 0; u < 2; u++) {
        const int j = t + 128 * u;
        lf[u] = rels[(b * S_ + i) * S_ + j];
        lr[u] = g_relsT[(b * S_ + i) * S_ + j];
        if (lf[u] > 0) atomicAdd(&cf[lf[u]], 1);
        if (lr[u] > 0) atomicAdd(&cr[lr[u]], 1);
    }
    __syncthreads();

    if (t < 32) {
        inv_f[t] = 1.0f / (float)(cf[t] > 0 ? cf[t] : 1);
        inv_r[t] = 1.0f / (float)(cr[t] > 0 ? cr[t] : 1);
    }
    __syncthreads();

    #pragma unroll
    for (int u = 0; u < 2; u++) {
        const int j = t + 128 * u;
        float w[4] = {0.f, 0.f, 0.f, 0.f};
        if (lf[u] > 0) {
            const float s = inv_f[lf[u]];
            #pragma unroll
            for (int c = 0; c < 4; c++) w[c] += rw[lf[u] * 4 + c] * s;
        }
        if (lr[u] > 0) {
            const float s = inv_r[lr[u]];
            #pragma unroll
            for (int c = 0; c < 4; c++) w[c] += rw[(lr[u] + 32) * 4 + c] * s;
        }
        #pragma unroll
        for (int c = 0; c < 4; c++)
            g_W[((size_t)(b * S_ + i)) * KW + c * 256 + j] = __float2half(w[c]);
    }
    __syncthreads();
}

__device__ void hb_item(float* __restrict__ out, int item, int t, char* sm) {
    const int n0 = (item % 30) * 128;    // never straddles a 768-slot
    const int m0 = (item / 30) * 64;
    const int cslot = n0 / 768;
    const int o0 = n0 - cslot * 768;

    const __half* A  = g_h + (size_t)m0 * H_;
    const __half* Bm = (cslot < 4) ? g_bas + (size_t)cslot * H_ * H_ + o0
                                   : g_self + o0;

    const int lane = t & 31, wid = t >> 5;
    const int wm = wid & 1, wn = wid >> 1;
    const uint32_t smb = s2u(sm);

    float acc[2][8][4] = {};
    const int NC = 24;
    #pragma unroll 1
    for (int p = 0; p < 2; p++) {
        const int k0 = p * 32;
        const uint32_t st = smb + (uint32_t)p * HB_STG;
        ld_a32(A + k0, H_, st, t);
        ld_b32<128, HB_BP>(Bm + (size_t)k0 * H_, H_, st + HB_ABUF, t);
        asm volatile("cp.async.commit_group;" ::: "memory");
    }
    for (int c = 0; c < NC; c++) {
        asm volatile("cp.async.wait_group 1;" ::: "memory");
        __syncthreads();
        const uint32_t st = smb + (uint32_t)(c % 3) * HB_STG;
        sub_t<HB_BP, 4>(st, st + HB_ABUF, acc, lane, wm, wn);
        sub_t<HB_BP, 4>(st + 32, st + HB_ABUF + 16 * HB_BP, acc, lane, wm, wn);
        if (c + 2 < NC) {
            const int k0 = (c + 2) * 32;
            const uint32_t sn = smb + (uint32_t)((c + 2) % 3) * HB_STG;
            ld_a32(A + k0, H_, sn, t);
            ld_b32<128, HB_BP>(Bm + (size_t)k0 * H_, H_, sn + HB_ABUF, t);
        }
        asm volatile("cp.async.commit_group;" ::: "memory");
    }

    if (cslot < 4) {
        __half* dst = g_hb2 + (size_t)cslot * (B_ * S_ * H_);
        #pragma unroll
        for (int mt = 0; mt < 2; mt++)
            #pragma unroll
            for (int nv = 0; nv < 8; nv++) {
                const int row = m0 + wm * 32 + mt * 16 + (lane >> 2);
                const int col = o0 + wn * 64 + nv * 8 + (lane & 3) * 2;
                *reinterpret_cast<__half2*>(dst + (size_t)row * H_ + col) =
                    __floats2half2_rn(acc[mt][nv][0], acc[mt][nv][1]);
                *reinterpret_cast<__half2*>(dst + (size_t)(row + 8) * H_ + col) =
                    __floats2half2_rn(acc[mt][nv][2], acc[mt][nv][3]);
            }
    } else {
        #pragma unroll
        for (int mt = 0; mt < 2; mt++)
            #pragma unroll
            for (int nv = 0; nv < 8; nv++) {
                const int row = m0 + wm * 32 + mt * 16 + (lane >> 2);
                const int col = o0 + wn * 64 + nv * 8 + (lane & 3) * 2;
                float2 v0, v1;
                v0.x = acc[mt][nv][0]; v0.y = acc[mt][nv][1];
                v1.x = acc[mt][nv][2]; v1.y = acc[mt][nv][3];
                *reinterpret_cast<float2*>(out + (size_t)row * H_ + col) = v0;
                *reinterpret_cast<float2*>(out + (size_t)(row + 8) * H_ + col) = v1;
            }
    }
    asm volatile("cp.async.wait_group 0;" ::: "memory");
    __syncthreads();
}

// ---------------- phase-3 items (gemm_out, split-K 2, red2) -------------------
#define P3_ITEMS 384   // 12 x 16 x 2

__device__ void out_item(float* __restrict__ out, int item, int t, char* sm) {
    const int n0 = (item % 12) * 64;
    const int row0 = ((item / 12) % 16) * 64;
    const int kc = item / 192;
    const int b = row0 >> 8;

    const __half* A = g_W + (size_t)row0 * KW + kc * 512;
    const __half* Bbase = g_hb2 + (size_t)(kc * 2) * (B_ * S_ * H_)
                        + (size_t)b * S_ * H_ + n0;

    const int lane = t & 31, wid = t >> 5;
    const int wm = wid & 1, wn = wid >> 1;
    const uint32_t smb = s2u(sm);

    float acc[2][4][4] = {};
    const int NC = 16;
    #pragma unroll 1
    for (int p = 0; p < 2; p++) {
        const int k0 = p * 32;
        const size_t boff = (size_t)(k0 >> 8) * (B_ * S_ * H_) + (size_t)(k0 & 255) * H_;
        const uint32_t st = smb + (uint32_t)p * OUT_STG;
        ld_a32(A + k0, KW, st, t);
        ld_b32<64, OUT_BP>(Bbase + boff, H_, st + HB_ABUF, t);
        asm volatile("cp.async.commit_group;" ::: "memory");
    }
    for (int c = 0; c < NC; c++) {
        asm volatile("cp.async.wait_group 1;" ::: "memory");
        __syncthreads();
        const uint32_t st = smb + (uint32_t)(c % 3) * OUT_STG;
        sub_t<OUT_BP, 2>(st, st + HB_ABUF, acc, lane, wm, wn);
        sub_t<OUT_BP, 2>(st + 32, st + HB_ABUF + 16 * OUT_BP, acc, lane, wm, wn);
        if (c + 2 < NC) {
            const int k0 = (c + 2) * 32;
            const size_t boff = (size_t)(k0 >> 8) * (B_ * S_ * H_) + (size_t)(k0 & 255) * H_;
            const uint32_t sn = smb + (uint32_t)((c + 2) % 3) * OUT_STG;
            ld_a32(A + k0, KW, sn, t);
            ld_b32<64, OUT_BP>(Bbase + boff, H_, sn + HB_ABUF, t);
        }
        asm volatile("cp.async.commit_group;" ::: "memory");
    }

    #pragma unroll
    for (int mt = 0; mt < 2; mt++)
        #pragma unroll
        for (int nv = 0; nv < 4; nv++) {
            const int row = row0 + wm * 32 + mt * 16 + (lane >> 2);
            const int col = n0 + wn * 32 + nv * 8 + (lane & 3) * 2;
            red2(out + (size_t)row * H_ + col,       acc[mt][nv][0], acc[mt][nv][1]);
            red2(out + (size_t)(row + 8) * H_ + col, acc[mt][nv][2], acc[mt][nv][3]);
        }
    asm volatile("cp.async.wait_group 0;" ::: "memory");
    __syncthreads();
}

// ---------------------------------------------------------------------------
// Persistent mega-kernel: prep | barrier | hb+build_w | barrier | out
// ---------------------------------------------------------------------------
__global__ __launch_bounds__(128, 4) void mega_kernel(
    float* __restrict__ out,
    const float* __restrict__ hidden, const float* __restrict__ basic,
    const float* __restrict__ selfw, const int* __restrict__ rels,
    const float* __restrict__ rel_weight)
{
    __shared__ __align__(128) char sm[SMEM_BYTES];
    const int t = threadIdx.x;
    unsigned lsense = 0;

    // ---- phase 1: prep ----
    for (int it = blockIdx.x; it < P1_ITEMS; it += NBLK) {
        if (it < P1_CONV_H)                      conv_item(hidden, g_h, it, t);
        else if (it < P1_CONV_H + P1_CONV_B)     conv_item(basic, g_bas, it - P1_CONV_H, t);
        else if (it < P1_CONV_H + P1_CONV_B + P1_SELF)
            self_item(selfw, it - P1_CONV_H - P1_CONV_B, t, sm);
        else
            rels_item(rels, it - P1_CONV_H - P1_CONV_B - P1_SELF, t, sm);
    }
    grid_barrier(&lsense);

    // ---- phase 2: hb GEMM + build_w ----
    for (int it = blockIdx.x; it < P2_ITEMS; it += NBLK) {
        if (it < P2_HB) hb_item(out, it, t, sm);
        else            bw_item(rels, rel_weight, it - P2_HB, t, sm);
    }
    grid_barrier(&lsense);

    // ---- phase 3: out GEMM ----
    for (int it = blockIdx.x; it < P3_ITEMS; it += NBLK)
        out_item(out, it, t, sm);
}

// ---------------------------------------------------------------------------
extern "C" void kernel_launch(void* const* d_in, const int* in_sizes, int n_in,
                              void* d_out, int out_size) {
    const float* hidden     = (const float*)d_in[0]; // [4,256,768]
    const int*   rels       = (const int*)  d_in[1]; // [4,256,256]
    const float* basic      = (const float*)d_in[2]; // [4,768,768]
    const float* rel_weight = (const float*)d_in[3]; // [64,4]
    const float* self_w     = (const float*)d_in[4]; // [768,768] (out,in)
    float* out = (float*)d_out;                      // [4,256,768]

    mega_kernel<<<NBLK, 128>>>(out, hidden, basic, self_w, rels, rel_weight);
}